// round 4
// baseline (speedup 1.0000x reference)
#include <cuda_runtime.h>
#include <math.h>

#define N 2048
#define D 768
#define SCALE 0.036084391824351615f  /* 1/sqrt(768) */

#define NB 64
#define NT 512
#define NWARP (NT/32)     /* 16 */
#define RPB (D / NB)      /* 12 rows per block */
#define GW (NB * NWARP)   /* 1024 global warps */
#define NGRP 8
#define GSZ (NB / NGRP)   /* 8 blocks per group */
#define LCAP 40           /* list capacity per block (ceil(2047/64)=32 max) */

/* dynamic smem layout (float slots) */
#define OFF_M      0
#define OFF_MW     (RPB*D)
#define OFF_WV2    (2*RPB*D)
#define OFF_VINTRA (3*RPB*D)
#define OFF_PN     (3*RPB*D + D)
#define OFF_VTMP   (3*RPB*D + 2*D)
#define OFF_Q1     (3*RPB*D + 3*D)
#define OFF_Z2     (3*RPB*D + 4*D)
#define OFF_TMPI   (3*RPB*D + 5*D)            /* 2048 ints */
#define SMEM_FLOATS (3*RPB*D + 5*D + N)
#define SMEM_BYTES  (SMEM_FLOATS * 4)

// ---------------- device globals ----------------
__device__ float g_K1[N*D];
__device__ float g_V1[N*D];
__device__ float g_D1[N*D];   // scale*(U@WD^T + bD)
__device__ float g_Q2[N*D];
__device__ float g_Z2[N*D];   // scale*(Q2@Wk2)
__device__ float g_M [D*D];   // scale*(Wq1 @ W_intra[:, :D])
__device__ float g_MW[D*D];   // g_M @ Wv2
__device__ float g_WD[D*D];
__device__ float g_WQ[D*D];
__device__ float g_bD[D];
__device__ float g_bQ[D];
__device__ float g_Mb[D];     // g_M @ bv2
__device__ float g_c2[N];
__device__ float g_q1[D];
__device__ float g_vacc1[2][D];
__device__ float g_vaccP[2][D];
__device__ float g_sum1[2];
__device__ float g_sum2[2];
__device__ int   g_tmp[N];
__device__ unsigned long long g_grp[NGRP];
__device__ unsigned long long g_root;

// ---------------- helpers ----------------
__device__ __forceinline__ float wreduce(float a) {
    #pragma unroll
    for (int o = 16; o; o >>= 1) a += __shfl_xor_sync(0xffffffffu, a, o);
    return a;
}

// two-level (8x8) tree barrier, monotonic counters
__device__ __forceinline__ void grid_bar(int b, unsigned long long& nbar) {
    __syncthreads();
    if (threadIdx.x == 0) {
        __threadfence();
        const int g = b >> 3;
        const unsigned long long e1 = nbar + 1;
        if (atomicAdd(&g_grp[g], 1ULL) + 1ULL == e1 * GSZ)
            atomicAdd(&g_root, 1ULL);
        const unsigned long long rtgt = e1 * NGRP;
        volatile unsigned long long* p = &g_root;
        while (*p < rtgt) { }
        __threadfence();
    }
    nbar++;
    __syncthreads();
}

// ---------------- last_same ----------------
__global__ void k_lastsame(const int* __restrict__ spk) {
    int i = blockIdx.x * blockDim.x + threadIdx.x;
    if (i < N) {
        int s = spk[i], r = -1;
        for (int j = i - 1; j >= 0; j--)
            if (spk[j] == s) { r = j; break; }
        g_tmp[i] = r;
    }
}

// ---------------- per-launch reset (graph replays) ----------------
__global__ void k_init() {
    int t = threadIdx.x;
    if (t == 0) {
        g_root = 0ULL;
        g_sum1[0] = g_sum1[1] = 0.f;
        g_sum2[0] = g_sum2[1] = 0.f;
    }
    if (t < NGRP) g_grp[t] = 0ULL;
    for (int c = t; c < D; c += blockDim.x) {
        g_vacc1[0][c] = 0.f; g_vacc1[1][c] = 0.f;
        g_vaccP[0][c] = 0.f; g_vaccP[1][c] = 0.f;
    }
}

// ---------------- combined biases ----------------
__global__ void k_biascomb(const float* __restrict__ Wq1, const float* __restrict__ bq1,
                           const float* __restrict__ b_intra,
                           const float* __restrict__ Wq2, const float* __restrict__ bq2,
                           const float* __restrict__ b_inter) {
    int r = blockIdx.x * blockDim.x + threadIdx.x;
    if (r < D) {
        float s1 = bq1[r], s2 = bq2[r];
        for (int m = 0; m < D; m++) {
            s1 += Wq1[(size_t)r*D + m] * b_intra[m];
            s2 += Wq2[(size_t)r*D + m] * b_inter[m];
        }
        g_bD[r] = s1; g_bQ[r] = s2;
    }
}

// ---------------- rowdot: out[i] = alpha * dot(A[i,:D], x) ----------------
__global__ void k_rowdot(const float* __restrict__ A, const float* __restrict__ x,
                         float* __restrict__ out, int M, float alpha) {
    int row = blockIdx.x * 8 + (threadIdx.x >> 5);
    int lane = threadIdx.x & 31;
    if (row < M) {
        float a = 0.f;
        for (int k = lane; k < D; k += 32) a += A[(size_t)row*D + k] * x[k];
        a = wreduce(a);
        if (lane == 0) out[row] = alpha * a;
    }
}

// ---------------- GEMM C = alpha*(A[M,K] @ W[Nc,K]^T + bias) ----------------
#define GBM 64
#define GBN 64
#define GBK 16
__global__ void __launch_bounds__(256)
k_gemm_nt(const float* __restrict__ A, const float* __restrict__ W,
          const float* __restrict__ bias, float* __restrict__ C,
          int Kc, float alpha) {
    __shared__ float As[GBM][GBK + 1];
    __shared__ float Ws[GBN][GBK + 1];
    const int t = threadIdx.x;
    const int tx = t & 15, ty = t >> 4;
    const int m0 = blockIdx.y * GBM, n0 = blockIdx.x * GBN;
    float acc[4][4] = {};
    for (int k0 = 0; k0 < Kc; k0 += GBK) {
        for (int x = t; x < GBM*GBK; x += 256) {
            int m = x >> 4, k = x & 15;
            As[m][k] = A[(size_t)(m0 + m)*Kc + k0 + k];
        }
        for (int x = t; x < GBN*GBK; x += 256) {
            int n = x >> 4, k = x & 15;
            Ws[n][k] = W[(size_t)(n0 + n)*Kc + k0 + k];
        }
        __syncthreads();
        #pragma unroll
        for (int kk = 0; kk < GBK; kk++) {
            float a[4], w[4];
            #pragma unroll
            for (int u = 0; u < 4; u++) a[u] = As[ty*4 + u][kk];
            #pragma unroll
            for (int v = 0; v < 4; v++) w[v] = Ws[tx*4 + v][kk];
            #pragma unroll
            for (int u = 0; u < 4; u++)
                #pragma unroll
                for (int v = 0; v < 4; v++) acc[u][v] += a[u] * w[v];
        }
        __syncthreads();
    }
    #pragma unroll
    for (int u = 0; u < 4; u++)
        #pragma unroll
        for (int v = 0; v < 4; v++) {
            int m = m0 + ty*4 + u, n = n0 + tx*4 + v;
            C[(size_t)m*D + n] = alpha * (acc[u][v] + bias[n]);
        }
}

// ---------------- GEMM C = alpha*(A[:,D] @ B[:, boff:boff+D]) ----------------
__global__ void __launch_bounds__(256)
k_gemm_ab(const float* __restrict__ A, const float* __restrict__ B,
          int ldb, int boff, float* __restrict__ C, float alpha) {
    __shared__ float As[GBM][GBK + 1];
    __shared__ float Bs[GBK][GBN];
    const int t = threadIdx.x;
    const int tx = t & 15, ty = t >> 4;
    const int m0 = blockIdx.y * GBM, n0 = blockIdx.x * GBN;
    float acc[4][4] = {};
    for (int k0 = 0; k0 < D; k0 += GBK) {
        for (int x = t; x < GBM*GBK; x += 256) {
            int m = x >> 4, k = x & 15;
            As[m][k] = A[(size_t)(m0 + m)*D + k0 + k];
        }
        for (int x = t; x < GBK*GBN; x += 256) {
            int k = x >> 6, n = x & 63;
            Bs[k][n] = B[(size_t)(k0 + k)*ldb + boff + n0 + n];
        }
        __syncthreads();
        #pragma unroll
        for (int kk = 0; kk < GBK; kk++) {
            float a[4], w[4];
            #pragma unroll
            for (int u = 0; u < 4; u++) a[u] = As[ty*4 + u][kk];
            #pragma unroll
            for (int v = 0; v < 4; v++) w[v] = Bs[kk][tx*4 + v];
            #pragma unroll
            for (int u = 0; u < 4; u++)
                #pragma unroll
                for (int v = 0; v < 4; v++) acc[u][v] += a[u] * w[v];
        }
        __syncthreads();
    }
    #pragma unroll
    for (int u = 0; u < 4; u++)
        #pragma unroll
        for (int v = 0; v < 4; v++)
            C[(size_t)(m0 + ty*4 + u)*D + n0 + tx*4 + v] = alpha * acc[u][v];
}

// ---------------- main recurrence ----------------
__global__ void __launch_bounds__(NT, 1)
k_main(const float* __restrict__ U,
       const float* __restrict__ Wv2, const float* __restrict__ bv2,
       float* __restrict__ Vout) {
    extern __shared__ float sm[];
    float* sM      = sm + OFF_M;
    float* sMW     = sm + OFF_MW;
    float* sWv2    = sm + OFF_WV2;
    float* sVintra = sm + OFF_VINTRA;
    float* sPn     = sm + OFF_PN;
    float* sVtmp   = sm + OFF_VTMP;
    float* sQ1     = sm + OFF_Q1;
    float* sZ2     = sm + OFF_Z2;
    int*   sTmpI   = (int*)(sm + OFF_TMPI);

    __shared__ float sE1[LCAP], sE2[LCAP];
    __shared__ int   sJ1[LCAP], sJ2[LCAP];
    __shared__ int   sCnt1, sCnt2;
    __shared__ float sSum1, sSum2;

    const int b = blockIdx.x, t = threadIdx.x;
    const int warp = t >> 5, lane = t & 31;
    const int r0 = b * RPB;

    // one-time: persistent weight rows + tmp[] into SMEM
    for (int x = t; x < RPB*D; x += NT) {
        sM[x]   = g_M [(size_t)r0*D + x];
        sMW[x]  = g_MW[(size_t)r0*D + x];
        sWv2[x] = Wv2[(size_t)r0*D + x];
    }
    for (int x = t; x < N; x += NT) sTmpI[x] = g_tmp[x];
    __syncthreads();

    unsigned long long nbar = 0;

    for (int i = 0; i <= N; i++) {
        const int tmp = (i < N) ? sTmpI[i] : -1;

        // ================= Phase A : finalize v_{i-1}; distributed q1 =================
        if (i > 0) {
            const int im1 = i - 1;
            const int tprev = sTmpI[im1];
            const int qa = im1 & 1;
            const bool hv = (tprev >= 0);
            const bool lazy = (tmp == im1);
            const float inv1 = hv ? 1.0f / g_sum1[qa] : 0.f;
            const float inv2 = hv ? 1.0f / g_sum2[qa] : 0.f;
            for (int c = t; c < D; c += NT) {
                sVintra[c] = hv ? g_vacc1[qa][c] * inv1 : U[(size_t)im1*D + c];
                sPn[c]     = hv ? g_vaccP[qa][c] * inv2 : 0.f;
            }
            if (tmp >= 0 && !lazy)
                for (int c = t; c < D; c += NT) sVtmp[c] = Vout[(size_t)tmp*D + c];
            __syncthreads();

            for (int rr = warp; rr < 2*RPB; rr += NWARP) {
                if (rr < RPB) {
                    // v_{i-1}[r0+rr] = v_intra + Wv2[r]·Pn (+ bv2)
                    const float* w = sWv2 + rr*D;
                    float a = 0.f;
                    #pragma unroll 4
                    for (int k = lane; k < D; k += 32) a += w[k] * sPn[k];
                    a = wreduce(a);
                    if (lane == 0) {
                        float v = a + sVintra[r0 + rr];
                        if (hv) v += bv2[r0 + rr];
                        Vout[(size_t)im1*D + r0 + rr] = v;
                    }
                } else if (tmp >= 0) {
                    const int r = rr - RPB;
                    const float* mrow = sM + r*D;
                    float a = 0.f;
                    if (lazy) {
                        const float* mwrow = sMW + r*D;
                        #pragma unroll 4
                        for (int k = lane; k < D; k += 32)
                            a += mrow[k] * sVintra[k] + mwrow[k] * sPn[k];
                    } else {
                        #pragma unroll 4
                        for (int k = lane; k < D; k += 32) a += mrow[k] * sVtmp[k];
                    }
                    a = wreduce(a);
                    if (lane == 0) {
                        float q = a + g_D1[(size_t)i*D + r0 + r];
                        if (lazy && hv) q += g_Mb[r0 + r];
                        g_q1[r0 + r] = q;
                    }
                }
            }
        }
        grid_bar(b, nbar);
        if (i == N) break;

        // ================= Phase B : scores (B1) + column accumulation (B2) =================
        {
            const int p = i & 1, z = p ^ 1;
            const int gid = b*NT + t;
            if (gid < D) { g_vacc1[z][gid] = 0.f; g_vaccP[z][gid] = 0.f; }
            else if (gid == D) { g_sum1[z] = 0.f; g_sum2[z] = 0.f; }

            if (tmp >= 0) {
                for (int c = t; c < D; c += NT) {
                    sQ1[c] = g_q1[c];
                    sZ2[c] = g_Z2[(size_t)i*D + c];
                }
                if (t == 0) { sCnt1 = 0; sCnt2 = 0; sSum1 = 0.f; sSum2 = 0.f; }
                __syncthreads();

                const float c2i = g_c2[i];
                const float4* q1v = (const float4*)sQ1;
                const float4* z2v = (const float4*)sZ2;

                // ---- B1: intra scores (K1 rows) ----
                float lsum1 = 0.f;
                for (int j = b*NWARP + warp; j <= i; j += GW) {
                    const float4* kr = (const float4*)(g_K1 + (size_t)j*D);
                    float acc = 0.f;
                    #pragma unroll
                    for (int u = 0; u < 6; u++) {
                        float4 kk = kr[lane + 32*u];
                        float4 qq = q1v[lane + 32*u];
                        acc += kk.x*qq.x + kk.y*qq.y + kk.z*qq.z + kk.w*qq.w;
                    }
                    acc = wreduce(acc);
                    const float e = __expf(acc);
                    if (lane == 0) {
                        int idx = atomicAdd(&sCnt1, 1);
                        sJ1[idx] = j; sE1[idx] = e; lsum1 += e;
                    }
                }
                if (lane == 0 && lsum1 != 0.f) atomicAdd(&sSum1, lsum1);

                // ---- B1: inter scores (Vout rows in [tmp, i)) ----
                float lsum2 = 0.f;
                for (int j = tmp + b*NWARP + warp; j < i; j += GW) {
                    const float4* vr = (const float4*)(Vout + (size_t)j*D);
                    float acc = 0.f;
                    #pragma unroll
                    for (int u = 0; u < 6; u++) {
                        float4 vv = vr[lane + 32*u];
                        float4 zz = z2v[lane + 32*u];
                        acc += vv.x*zz.x + vv.y*zz.y + vv.z*zz.z + vv.w*zz.w;
                    }
                    acc = wreduce(acc);
                    const float e = __expf(acc + c2i);
                    if (lane == 0) {
                        int idx = atomicAdd(&sCnt2, 1);
                        sJ2[idx] = j; sE2[idx] = e; lsum2 += e;
                    }
                }
                if (lane == 0 && lsum2 != 0.f) atomicAdd(&sSum2, lsum2);
                __syncthreads();

                // ---- B2: column-parallel accumulation, one global atomic per column ----
                const int n1 = sCnt1, n2 = sCnt2;
                for (int c = t; c < D; c += NT) {
                    if (n1) {
                        float a1 = 0.f;
                        for (int k = 0; k < n1; k++)
                            a1 += sE1[k] * g_V1[(size_t)sJ1[k]*D + c];
                        atomicAdd(&g_vacc1[p][c], a1);
                    }
                    if (n2) {
                        float aP = 0.f;
                        for (int k = 0; k < n2; k++)
                            aP += sE2[k] * Vout[(size_t)sJ2[k]*D + c];
                        atomicAdd(&g_vaccP[p][c], aP);
                    }
                }
                if (t == 0) {
                    if (sSum1 != 0.f) atomicAdd(&g_sum1[p], sSum1);
                    if (sSum2 != 0.f) atomicAdd(&g_sum2[p], sSum2);
                }
            }
        }
        grid_bar(b, nbar);
    }
}

// ---------------- launch ----------------
extern "C" void kernel_launch(void* const* d_in, const int* in_sizes, int n_in,
                              void* d_out, int out_size) {
    const float* U       = (const float*)d_in[0];
    const int*   spk     = (const int*)  d_in[1];
    const float* W_intra = (const float*)d_in[2];
    const float* b_intra = (const float*)d_in[3];
    const float* W_inter = (const float*)d_in[4];
    const float* b_inter = (const float*)d_in[5];
    const float* Wq1 = (const float*)d_in[6];  const float* bq1 = (const float*)d_in[7];
    const float* Wk1 = (const float*)d_in[8];  const float* bk1 = (const float*)d_in[9];
    const float* Wv1 = (const float*)d_in[10]; const float* bv1 = (const float*)d_in[11];
    const float* Wq2 = (const float*)d_in[12]; const float* bq2 = (const float*)d_in[13];
    const float* Wk2 = (const float*)d_in[14]; const float* bk2 = (const float*)d_in[15];
    const float* Wv2 = (const float*)d_in[16]; const float* bv2 = (const float*)d_in[17];
    float* Vout = (float*)d_out;
    (void)in_sizes; (void)n_in; (void)out_size;

    float *pM, *pMW, *pWD, *pWQ, *pbD, *pbQ, *pMb, *pc2;
    float *pK1, *pV1, *pD1, *pQ2, *pZ2;
    cudaGetSymbolAddress((void**)&pM,  g_M);
    cudaGetSymbolAddress((void**)&pMW, g_MW);
    cudaGetSymbolAddress((void**)&pWD, g_WD);
    cudaGetSymbolAddress((void**)&pWQ, g_WQ);
    cudaGetSymbolAddress((void**)&pbD, g_bD);
    cudaGetSymbolAddress((void**)&pbQ, g_bQ);
    cudaGetSymbolAddress((void**)&pMb, g_Mb);
    cudaGetSymbolAddress((void**)&pc2, g_c2);
    cudaGetSymbolAddress((void**)&pK1, g_K1);
    cudaGetSymbolAddress((void**)&pV1, g_V1);
    cudaGetSymbolAddress((void**)&pD1, g_D1);
    cudaGetSymbolAddress((void**)&pQ2, g_Q2);
    cudaGetSymbolAddress((void**)&pZ2, g_Z2);

    cudaFuncSetAttribute(k_main, cudaFuncAttributeMaxDynamicSharedMemorySize, SMEM_BYTES);

    k_lastsame<<<(N + 255)/256, 256>>>(spk);
    k_init<<<1, 256>>>();
    k_biascomb<<<(D + 255)/256, 256>>>(Wq1, bq1, b_intra, Wq2, bq2, b_inter);

    dim3 gDD(D/GBN, D/GBM);
    k_gemm_ab<<<gDD, 256>>>(Wq1, W_intra, 2*D, 0, pM,  SCALE); // M (scaled)
    k_gemm_ab<<<gDD, 256>>>(Wq1, W_intra, 2*D, D, pWD, 1.0f);  // WD
    k_gemm_ab<<<gDD, 256>>>(Wq2, W_inter, D,   0, pWQ, 1.0f);  // WQ
    k_gemm_ab<<<gDD, 256>>>(pM,  Wv2,     D,   0, pMW, 1.0f);  // MW = M@Wv2
    k_rowdot<<<(D + 7)/8, 256>>>(pM, bv2, pMb, D, 1.0f);       // Mb = M@bv2

    dim3 gND(D/GBN, N/GBM);
    k_gemm_nt<<<gND, 256>>>(U, Wk1, bk1, pK1, D, 1.0f);        // K1
    k_gemm_nt<<<gND, 256>>>(U, Wv1, bv1, pV1, D, 1.0f);        // V1
    k_gemm_nt<<<gND, 256>>>(U, pWD, pbD, pD1, D, SCALE);       // D1 (scaled)
    k_gemm_nt<<<gND, 256>>>(U, pWQ, pbQ, pQ2, D, 1.0f);        // Q2
    k_gemm_ab<<<gND, 256>>>(pQ2, Wk2, D, 0, pZ2, SCALE);       // Z2 = scale*Q2@Wk2
    k_rowdot<<<(N + 7)/8, 256>>>(pQ2, bk2, pc2, N, SCALE);     // c2 (scaled)

    k_main<<<NB, NT, SMEM_BYTES>>>(U, Wv2, bv2, Vout);
}

// round 5
// speedup vs baseline: 1.2397x; 1.2397x over previous
#include <cuda_runtime.h>
#include <math.h>

#define N 2048
#define D 768
#define SCALE 0.036084391824351615f  /* 1/sqrt(768) */

#define NB 128
#define NT 512
#define NWARP (NT/32)     /* 16 */
#define RPB (D / NB)      /* 6 rows per block */
#define GW (NB * NWARP)   /* 2048 global warps */
#define NGRP 16
#define GSZ (NB / NGRP)   /* 8 */
#define LCAP 20

/* k_main dynamic smem layout (float slots) */
#define OFF_WV2   0
#define OFF_PN    (RPB*D)
#define OFF_VTMP  (RPB*D + D)
#define OFF_Z2    (RPB*D + 2*D)
#define OFF_TMPI  (RPB*D + 3*D)
#define SMEM_FLOATS (RPB*D + 3*D + N)
#define SMEM_BYTES  (SMEM_FLOATS * 4)

// ---------------- device globals ----------------
__device__ float g_K1[N*D];
__device__ float g_V1[N*D];
__device__ float g_D1[N*D];            // scale*(U@WD^T + bD)
__device__ float g_Q2[N*D];
__device__ float g_Z2[N*D];            // scale*(Q2@Wk2)
__device__ float g_KM[N*D];            // K1 @ M   (M already scaled)
__device__ float g_S1b[(size_t)N*N];   // D1 @ K1^T
__device__ float g_M [D*D];            // scale*(Wq1 @ W_intra[:, :D])
__device__ float g_WD[D*D];            // Wq1 @ W_intra[:, D:]
__device__ float g_WQ[D*D];            // Wq2 @ W_inter
__device__ float g_bD[D];
__device__ float g_bQ[D];
__device__ float g_vacc1[2][D];
__device__ float g_vaccP[2][D];
__device__ float g_sum1[2];
__device__ float g_sum2[2];
__device__ int   g_tmp[N];
__device__ unsigned long long g_grp[NGRP];
__device__ unsigned long long g_root;

// ---------------- helpers ----------------
__device__ __forceinline__ float wreduce(float a) {
    #pragma unroll
    for (int o = 16; o; o >>= 1) a += __shfl_xor_sync(0xffffffffu, a, o);
    return a;
}

// two-level (16 x 8) tree barrier, monotonic counters
__device__ __forceinline__ void grid_bar(int b, unsigned long long& nbar) {
    __syncthreads();
    if (threadIdx.x == 0) {
        __threadfence();
        const int g = b >> 3;
        const unsigned long long e1 = nbar + 1;
        if (atomicAdd(&g_grp[g], 1ULL) + 1ULL == e1 * GSZ)
            atomicAdd(&g_root, 1ULL);
        const unsigned long long rtgt = e1 * NGRP;
        volatile unsigned long long* p = &g_root;
        while (*p < rtgt) { }
        __threadfence();
    }
    nbar++;
    __syncthreads();
}

// ================= setup: last_same + combined biases + state reset =================
__global__ void __launch_bounds__(NT)
k_setup(const int* __restrict__ spk,
        const float* __restrict__ Wq1, const float* __restrict__ bq1,
        const float* __restrict__ b_intra,
        const float* __restrict__ Wq2, const float* __restrict__ bq2,
        const float* __restrict__ b_inter) {
    const int b = blockIdx.x, t = threadIdx.x;
    if (b < 4) {
        // last_same back-scan
        int i = b * NT + t;
        int s = spk[i], r = -1;
        for (int j = i - 1; j >= 0; j--)
            if (spk[j] == s) { r = j; break; }
        g_tmp[i] = r;
    } else if (b < 100) {
        // bD / bQ : warp-per-row
        const int rid = (b - 4) * NWARP + (t >> 5);   // 0..1535
        const int lane = t & 31;
        if (rid < 2 * D) {
            const int mat = rid >= D;
            const int r = mat ? rid - D : rid;
            const float* W  = mat ? Wq2 : Wq1;
            const float* bv = mat ? b_inter : b_intra;
            float a = 0.f;
            for (int k = lane; k < D; k += 32) a += W[(size_t)r*D + k] * bv[k];
            a = wreduce(a);
            if (lane == 0) {
                if (mat) g_bQ[r] = a + bq2[r];
                else     g_bD[r] = a + bq1[r];
            }
        }
    } else {
        // state reset (graph replays!)
        if (t == 0) {
            g_root = 0ULL;
            g_sum1[0] = g_sum1[1] = 0.f;
            g_sum2[0] = g_sum2[1] = 0.f;
        }
        if (t < NGRP) g_grp[t] = 0ULL;
        for (int c = t; c < D; c += NT) {
            g_vacc1[0][c] = 0.f; g_vacc1[1][c] = 0.f;
            g_vaccP[0][c] = 0.f; g_vaccP[1][c] = 0.f;
        }
    }
}

// ================= GEMM tiles =================
#define GBM 64
#define GBN 64
#define GBK 16

// ---- batched D x D : C = alpha * A @ B[:, off:off+D]  (ab form) ----
__global__ void __launch_bounds__(256)
k_gemmDD(const float* __restrict__ Wq1, const float* __restrict__ W_intra,
         const float* __restrict__ Wq2, const float* __restrict__ W_inter) {
    const float* A; const float* B; int ldb, off; float* C; float alpha;
    switch (blockIdx.z) {
        case 0:  A = Wq1; B = W_intra; ldb = 2*D; off = 0; C = g_M;  alpha = SCALE; break;
        case 1:  A = Wq1; B = W_intra; ldb = 2*D; off = D; C = g_WD; alpha = 1.f;   break;
        default: A = Wq2; B = W_inter; ldb = D;   off = 0; C = g_WQ; alpha = 1.f;   break;
    }
    __shared__ float As[GBM][GBK + 1];
    __shared__ float Bs[GBK][GBN];
    const int t = threadIdx.x;
    const int tx = t & 15, ty = t >> 4;
    const int m0 = blockIdx.y * GBM, n0 = blockIdx.x * GBN;
    float acc[4][4] = {};
    for (int k0 = 0; k0 < D; k0 += GBK) {
        for (int x = t; x < GBM*GBK; x += 256) {
            int m = x >> 4, k = x & 15;
            As[m][k] = A[(size_t)(m0 + m)*D + k0 + k];
        }
        for (int x = t; x < GBK*GBN; x += 256) {
            int k = x >> 6, n = x & 63;
            Bs[k][n] = B[(size_t)(k0 + k)*ldb + off + n0 + n];
        }
        __syncthreads();
        #pragma unroll
        for (int kk = 0; kk < GBK; kk++) {
            float a[4], w[4];
            #pragma unroll
            for (int u = 0; u < 4; u++) a[u] = As[ty*4 + u][kk];
            #pragma unroll
            for (int v = 0; v < 4; v++) w[v] = Bs[kk][tx*4 + v];
            #pragma unroll
            for (int u = 0; u < 4; u++)
                #pragma unroll
                for (int v = 0; v < 4; v++) acc[u][v] += a[u] * w[v];
        }
        __syncthreads();
    }
    #pragma unroll
    for (int u = 0; u < 4; u++)
        #pragma unroll
        for (int v = 0; v < 4; v++)
            C[(size_t)(m0 + ty*4 + u)*D + n0 + tx*4 + v] = alpha * acc[u][v];
}

// ---- batched N x D : C = alpha * (U @ W^T + bias)  (nt form) ----
__global__ void __launch_bounds__(256)
k_gemmND(const float* __restrict__ U,
         const float* __restrict__ Wk1, const float* __restrict__ bk1,
         const float* __restrict__ Wv1, const float* __restrict__ bv1) {
    const float* W; const float* bias; float* C; float alpha;
    switch (blockIdx.z) {
        case 0:  W = Wk1;  bias = bk1;  C = g_K1; alpha = 1.f;   break;
        case 1:  W = Wv1;  bias = bv1;  C = g_V1; alpha = 1.f;   break;
        case 2:  W = g_WD; bias = g_bD; C = g_D1; alpha = SCALE; break;
        default: W = g_WQ; bias = g_bQ; C = g_Q2; alpha = 1.f;   break;
    }
    __shared__ float As[GBM][GBK + 1];
    __shared__ float Ws[GBN][GBK + 1];
    const int t = threadIdx.x;
    const int tx = t & 15, ty = t >> 4;
    const int m0 = blockIdx.y * GBM, n0 = blockIdx.x * GBN;
    float acc[4][4] = {};
    for (int k0 = 0; k0 < D; k0 += GBK) {
        for (int x = t; x < GBM*GBK; x += 256) {
            int m = x >> 4, k = x & 15;
            As[m][k] = U[(size_t)(m0 + m)*D + k0 + k];
        }
        for (int x = t; x < GBN*GBK; x += 256) {
            int n = x >> 4, k = x & 15;
            Ws[n][k] = W[(size_t)(n0 + n)*D + k0 + k];
        }
        __syncthreads();
        #pragma unroll
        for (int kk = 0; kk < GBK; kk++) {
            float a[4], w[4];
            #pragma unroll
            for (int u = 0; u < 4; u++) a[u] = As[ty*4 + u][kk];
            #pragma unroll
            for (int v = 0; v < 4; v++) w[v] = Ws[tx*4 + v][kk];
            #pragma unroll
            for (int u = 0; u < 4; u++)
                #pragma unroll
                for (int v = 0; v < 4; v++) acc[u][v] += a[u] * w[v];
        }
        __syncthreads();
    }
    #pragma unroll
    for (int u = 0; u < 4; u++)
        #pragma unroll
        for (int v = 0; v < 4; v++) {
            int m = m0 + ty*4 + u, n = n0 + tx*4 + v;
            C[(size_t)m*D + n] = alpha * (acc[u][v] + bias[n]);
        }
}

// ---- batched post : z0: Z2 = scale*Q2@Wk2 ; z1: KM = K1@M  (ab form, N rows) ----
__global__ void __launch_bounds__(256)
k_gemmPost(const float* __restrict__ Wk2) {
    const float* A; const float* B; float* C; float alpha;
    if (blockIdx.z == 0) { A = g_Q2; B = Wk2; C = g_Z2; alpha = SCALE; }
    else                 { A = g_K1; B = g_M; C = g_KM; alpha = 1.f; }
    __shared__ float As[GBM][GBK + 1];
    __shared__ float Bs[GBK][GBN];
    const int t = threadIdx.x;
    const int tx = t & 15, ty = t >> 4;
    const int m0 = blockIdx.y * GBM, n0 = blockIdx.x * GBN;
    float acc[4][4] = {};
    for (int k0 = 0; k0 < D; k0 += GBK) {
        for (int x = t; x < GBM*GBK; x += 256) {
            int m = x >> 4, k = x & 15;
            As[m][k] = A[(size_t)(m0 + m)*D + k0 + k];
        }
        for (int x = t; x < GBK*GBN; x += 256) {
            int k = x >> 6, n = x & 63;
            Bs[k][n] = B[(size_t)(k0 + k)*D + n0 + n];
        }
        __syncthreads();
        #pragma unroll
        for (int kk = 0; kk < GBK; kk++) {
            float a[4], w[4];
            #pragma unroll
            for (int u = 0; u < 4; u++) a[u] = As[ty*4 + u][kk];
            #pragma unroll
            for (int v = 0; v < 4; v++) w[v] = Bs[kk][tx*4 + v];
            #pragma unroll
            for (int u = 0; u < 4; u++)
                #pragma unroll
                for (int v = 0; v < 4; v++) acc[u][v] += a[u] * w[v];
        }
        __syncthreads();
    }
    #pragma unroll
    for (int u = 0; u < 4; u++)
        #pragma unroll
        for (int v = 0; v < 4; v++)
            C[(size_t)(m0 + ty*4 + u)*D + n0 + tx*4 + v] = alpha * acc[u][v];
}

// ---- S1b = D1 @ K1^T  (N x N, nt form, no bias) ----
__global__ void __launch_bounds__(256)
k_gemmS1b() {
    __shared__ float As[GBM][GBK + 1];
    __shared__ float Ws[GBN][GBK + 1];
    const int t = threadIdx.x;
    const int tx = t & 15, ty = t >> 4;
    const int m0 = blockIdx.y * GBM, n0 = blockIdx.x * GBN;
    float acc[4][4] = {};
    for (int k0 = 0; k0 < D; k0 += GBK) {
        for (int x = t; x < GBM*GBK; x += 256) {
            int m = x >> 4, k = x & 15;
            As[m][k] = g_D1[(size_t)(m0 + m)*D + k0 + k];
        }
        for (int x = t; x < GBN*GBK; x += 256) {
            int n = x >> 4, k = x & 15;
            Ws[n][k] = g_K1[(size_t)(n0 + n)*D + k0 + k];
        }
        __syncthreads();
        #pragma unroll
        for (int kk = 0; kk < GBK; kk++) {
            float a[4], w[4];
            #pragma unroll
            for (int u = 0; u < 4; u++) a[u] = As[ty*4 + u][kk];
            #pragma unroll
            for (int v = 0; v < 4; v++) w[v] = Ws[tx*4 + v][kk];
            #pragma unroll
            for (int u = 0; u < 4; u++)
                #pragma unroll
                for (int v = 0; v < 4; v++) acc[u][v] += a[u] * w[v];
        }
        __syncthreads();
    }
    #pragma unroll
    for (int u = 0; u < 4; u++)
        #pragma unroll
        for (int v = 0; v < 4; v++)
            g_S1b[(size_t)(m0 + ty*4 + u)*N + n0 + tx*4 + v] = acc[u][v];
}

// ================= main recurrence: tiny Phase A + streaming Phase B =================
__global__ void __launch_bounds__(NT, 1)
k_main(const float* __restrict__ U,
       const float* __restrict__ Wv2, const float* __restrict__ bv2,
       float* __restrict__ Vout) {
    extern __shared__ float sm[];
    float* sWv2  = sm + OFF_WV2;
    float* sPn   = sm + OFF_PN;
    float* sVtmp = sm + OFF_VTMP;
    float* sZ2   = sm + OFF_Z2;
    int*   sTmpI = (int*)(sm + OFF_TMPI);

    __shared__ float sE1[LCAP], sE2[LCAP];
    __shared__ int   sJ1[LCAP], sJ2[LCAP];
    __shared__ int   sCnt1, sCnt2;
    __shared__ float sSum1, sSum2;

    const int b = blockIdx.x, t = threadIdx.x;
    const int warp = t >> 5, lane = t & 31;
    const int r0 = b * RPB;

    // one-time: Wv2 rows + tmp[] into SMEM
    for (int x = t; x < RPB*D; x += NT)
        sWv2[x] = Wv2[(size_t)r0*D + x];
    for (int x = t; x < N; x += NT) sTmpI[x] = g_tmp[x];
    __syncthreads();

    unsigned long long nbar = 0;

    for (int i = 0; i <= N; i++) {
        const int tmp = (i < N) ? sTmpI[i] : -1;

        // ===== Phase A : finalize V[i-1] =====
        if (i > 0) {
            const int im1 = i - 1;
            const int tprev = sTmpI[im1];
            const int qa = im1 & 1;
            if (tprev >= 0) {
                const float inv2 = 1.0f / g_sum2[qa];
                for (int c = t; c < D; c += NT)
                    sPn[c] = g_vaccP[qa][c] * inv2;
                __syncthreads();
                if (warp < RPB) {
                    const float* w = sWv2 + warp*D;
                    float a = 0.f;
                    #pragma unroll 4
                    for (int k = lane; k < D; k += 32) a += w[k] * sPn[k];
                    a = wreduce(a);
                    if (lane == 0) {
                        const int r = r0 + warp;
                        const float inv1 = 1.0f / g_sum1[qa];
                        Vout[(size_t)im1*D + r] = a + g_vacc1[qa][r]*inv1 + bv2[r];
                    }
                }
            } else {
                if (t < RPB)
                    Vout[(size_t)im1*D + r0 + t] = U[(size_t)im1*D + r0 + t];
            }
        }
        grid_bar(b, nbar);
        if (i == N) break;

        // ===== Phase B : scores + accumulation =====
        {
            const int p = i & 1, z = p ^ 1;
            const int gid = b*NT + t;
            if (gid < D) { g_vacc1[z][gid] = 0.f; g_vaccP[z][gid] = 0.f; }
            else if (gid == D) { g_sum1[z] = 0.f; g_sum2[z] = 0.f; }

            if (tmp >= 0) {
                for (int c = t; c < D; c += NT) {
                    sVtmp[c] = Vout[(size_t)tmp*D + c];
                    sZ2[c]   = g_Z2[(size_t)i*D + c];
                }
                if (t == 0) { sCnt1 = 0; sCnt2 = 0; sSum1 = 0.f; sSum2 = 0.f; }
                __syncthreads();

                const float4* vtv = (const float4*)sVtmp;
                const float4* z2v = (const float4*)sZ2;

                // intra scores: s1 = KM[j]·v_tmp + S1b[i,j]
                float lsum1 = 0.f;
                for (int j = b*NWARP + warp; j <= i; j += GW) {
                    const float4* kr = (const float4*)(g_KM + (size_t)j*D);
                    float acc = 0.f;
                    #pragma unroll
                    for (int u = 0; u < 6; u++) {
                        float4 kk = kr[lane + 32*u];
                        float4 qq = vtv[lane + 32*u];
                        acc += kk.x*qq.x + kk.y*qq.y + kk.z*qq.z + kk.w*qq.w;
                    }
                    acc = wreduce(acc);
                    if (lane == 0) {
                        const float e = __expf(acc + g_S1b[(size_t)i*N + j]);
                        int idx = atomicAdd(&sCnt1, 1);
                        sJ1[idx] = j; sE1[idx] = e; lsum1 += e;
                    }
                }
                if (lane == 0 && lsum1 != 0.f) atomicAdd(&sSum1, lsum1);

                // inter scores: s2 = Z2[i]·V[j]  (j in [tmp, i); uniform shift dropped)
                float lsum2 = 0.f;
                for (int j = tmp + b*NWARP + warp; j < i; j += GW) {
                    const float4* vr = (const float4*)(Vout + (size_t)j*D);
                    float acc = 0.f;
                    #pragma unroll
                    for (int u = 0; u < 6; u++) {
                        float4 vv = vr[lane + 32*u];
                        float4 zz = z2v[lane + 32*u];
                        acc += vv.x*zz.x + vv.y*zz.y + vv.z*zz.z + vv.w*zz.w;
                    }
                    acc = wreduce(acc);
                    if (lane == 0) {
                        const float e = __expf(acc);
                        int idx = atomicAdd(&sCnt2, 1);
                        sJ2[idx] = j; sE2[idx] = e; lsum2 += e;
                    }
                }
                if (lane == 0 && lsum2 != 0.f) atomicAdd(&sSum2, lsum2);
                __syncthreads();

                // column-parallel accumulation, one global atomic per column per block
                const int n1 = sCnt1, n2 = sCnt2;
                for (int c = t; c < D; c += NT) {
                    if (n1) {
                        float a1 = 0.f;
                        for (int k = 0; k < n1; k++)
                            a1 += sE1[k] * g_V1[(size_t)sJ1[k]*D + c];
                        atomicAdd(&g_vacc1[p][c], a1);
                    }
                    if (n2) {
                        float aP = 0.f;
                        for (int k = 0; k < n2; k++)
                            aP += sE2[k] * Vout[(size_t)sJ2[k]*D + c];
                        atomicAdd(&g_vaccP[p][c], aP);
                    }
                }
                if (t == 0) {
                    if (sSum1 != 0.f) atomicAdd(&g_sum1[p], sSum1);
                    if (sSum2 != 0.f) atomicAdd(&g_sum2[p], sSum2);
                }
            }
        }
        grid_bar(b, nbar);
    }
}

// ---------------- launch : k_main is the 6th launch (ncu -s 5 -c 1 captures it) ----------------
extern "C" void kernel_launch(void* const* d_in, const int* in_sizes, int n_in,
                              void* d_out, int out_size) {
    const float* U       = (const float*)d_in[0];
    const int*   spk     = (const int*)  d_in[1];
    const float* W_intra = (const float*)d_in[2];
    const float* b_intra = (const float*)d_in[3];
    const float* W_inter = (const float*)d_in[4];
    const float* b_inter = (const float*)d_in[5];
    const float* Wq1 = (const float*)d_in[6];  const float* bq1 = (const float*)d_in[7];
    const float* Wk1 = (const float*)d_in[8];  const float* bk1 = (const float*)d_in[9];
    const float* Wv1 = (const float*)d_in[10]; const float* bv1 = (const float*)d_in[11];
    const float* Wq2 = (const float*)d_in[12]; const float* bq2 = (const float*)d_in[13];
    const float* Wk2 = (const float*)d_in[14]; const float* bk2 = (const float*)d_in[15];
    const float* Wv2 = (const float*)d_in[16]; const float* bv2 = (const float*)d_in[17];
    float* Vout = (float*)d_out;
    (void)in_sizes; (void)n_in; (void)out_size; (void)bk2;

    cudaFuncSetAttribute(k_main, cudaFuncAttributeMaxDynamicSharedMemorySize, SMEM_BYTES);

    k_setup<<<101, NT>>>(spk, Wq1, bq1, b_intra, Wq2, bq2, b_inter);          // 1
    k_gemmDD<<<dim3(D/GBN, D/GBM, 3), 256>>>(Wq1, W_intra, Wq2, W_inter);     // 2
    k_gemmND<<<dim3(D/GBN, N/GBM, 4), 256>>>(U, Wk1, bk1, Wv1, bv1);          // 3
    k_gemmPost<<<dim3(D/GBN, N/GBM, 2), 256>>>(Wk2);                          // 4
    k_gemmS1b<<<dim3(N/GBN, N/GBM), 256>>>();                                 // 5
    k_main<<<NB, NT, SMEM_BYTES>>>(U, Wv2, bv2, Vout);                        // 6
}

// round 6
// speedup vs baseline: 1.6148x; 1.3025x over previous
#include <cuda_runtime.h>
#include <math.h>

#define N 2048
#define D 768
#define SCALE 0.036084391824351615f  /* 1/sqrt(768) */

#define NB 128
#define NT 512
#define NWARP (NT/32)     /* 16 */
#define RPB (D / NB)      /* 6 rows per block */
#define NGRP 16
#define GSZ (NB / NGRP)   /* 8 */
#define NSL 3             /* triple-buffered accumulators */

/* k_main dynamic smem layout (float slots) */
#define OFF_WV2   0
#define OFF_Y1    (RPB*D)
#define OFF_Y2    (RPB*D + D)
#define OFF_VT    (RPB*D + 2*D)
#define OFF_Z2    (RPB*D + 3*D)
#define OFF_TMPI  (RPB*D + 4*D)
#define SMEM_FLOATS (RPB*D + 4*D + N)
#define SMEM_BYTES  (SMEM_FLOATS * 4)

// ---------------- device globals ----------------
__device__ float g_K1[N*D];
__device__ float g_V1[N*D];
__device__ float g_D1[N*D];            // scale*(U@WD^T + bD)
__device__ float g_Q2[N*D];
__device__ float g_Z2[N*D];            // scale*(Q2@Wk2)
__device__ float g_KM[N*D];            // K1 @ M
__device__ float g_ZW[N*D];            // Z2 @ Wv2
__device__ float g_KMW[N*D];           // KM @ Wv2
__device__ float g_S1b[(size_t)N*N];   // D1 @ K1^T
__device__ float g_M [D*D];            // scale*(Wq1 @ W_intra[:, :D])
__device__ float g_WD[D*D];
__device__ float g_WQ[D*D];
__device__ float g_bD[D];
__device__ float g_bQ[D];
__device__ float g_vacc1[NSL][D];
__device__ float g_vaccV[NSL][D];
__device__ float g_sum1[NSL];
__device__ float g_sum2[NSL];
__device__ float g_phi[NSL];
__device__ int   g_tmp[N];
__device__ unsigned long long g_grp[NGRP];
__device__ unsigned long long g_root;

// ---------------- helpers ----------------
__device__ __forceinline__ float wreduce(float a) {
    #pragma unroll
    for (int o = 16; o; o >>= 1) a += __shfl_xor_sync(0xffffffffu, a, o);
    return a;
}

// warp dot over D=768 (192 float4 = 32 lanes x 6)
__device__ __forceinline__ float wdot(const float* __restrict__ a,
                                      const float* __restrict__ b, int lane) {
    const float4* A = (const float4*)a;
    const float4* B = (const float4*)b;
    float s = 0.f;
    #pragma unroll
    for (int u = 0; u < 6; u++) {
        float4 x = A[lane + 32*u], y = B[lane + 32*u];
        s += x.x*y.x + x.y*y.y + x.z*y.z + x.w*y.w;
    }
    return s;
}

// two-level (16 x 8) tree barrier, monotonic counters
__device__ __forceinline__ void grid_bar(int b, unsigned long long& nbar) {
    __syncthreads();
    if (threadIdx.x == 0) {
        __threadfence();
        const int g = b >> 3;
        const unsigned long long e1 = nbar + 1;
        if (atomicAdd(&g_grp[g], 1ULL) + 1ULL == e1 * GSZ)
            atomicAdd(&g_root, 1ULL);
        const unsigned long long rtgt = e1 * NGRP;
        volatile unsigned long long* p = &g_root;
        while (*p < rtgt) { }
        __threadfence();
    }
    nbar++;
    __syncthreads();
}

// ================= setup: last_same + combined biases + state reset =================
__global__ void __launch_bounds__(NT)
k_setup(const int* __restrict__ spk,
        const float* __restrict__ Wq1, const float* __restrict__ bq1,
        const float* __restrict__ b_intra,
        const float* __restrict__ Wq2, const float* __restrict__ bq2,
        const float* __restrict__ b_inter) {
    const int b = blockIdx.x, t = threadIdx.x;
    if (b < 4) {
        int i = b * NT + t;
        int s = spk[i], r = -1;
        for (int j = i - 1; j >= 0; j--)
            if (spk[j] == s) { r = j; break; }
        g_tmp[i] = r;
    } else if (b < 100) {
        const int rid = (b - 4) * NWARP + (t >> 5);
        const int lane = t & 31;
        if (rid < 2 * D) {
            const int mat = rid >= D;
            const int r = mat ? rid - D : rid;
            const float* W  = mat ? Wq2 : Wq1;
            const float* bv = mat ? b_inter : b_intra;
            float a = 0.f;
            for (int k = lane; k < D; k += 32) a += W[(size_t)r*D + k] * bv[k];
            a = wreduce(a);
            if (lane == 0) {
                if (mat) g_bQ[r] = a + bq2[r];
                else     g_bD[r] = a + bq1[r];
            }
        }
    } else {
        // state reset (graph replays!)
        if (t == 0) {
            g_root = 0ULL;
            for (int s = 0; s < NSL; s++) {
                g_sum1[s] = 0.f; g_sum2[s] = 0.f; g_phi[s] = 0.f;
            }
        }
        if (t < NGRP) g_grp[t] = 0ULL;
        for (int c = t; c < D; c += NT)
            for (int s = 0; s < NSL; s++) {
                g_vacc1[s][c] = 0.f; g_vaccV[s][c] = 0.f;
            }
    }
}

// ================= GEMM tiles =================
#define GBM 64
#define GBN 64
#define GBK 16

// ---- batched D x D : C = alpha * A @ B[:, off:off+D]  (ab form) ----
__global__ void __launch_bounds__(256)
k_gemmDD(const float* __restrict__ Wq1, const float* __restrict__ W_intra,
         const float* __restrict__ Wq2, const float* __restrict__ W_inter) {
    const float* A; const float* B; int ldb, off; float* C; float alpha;
    switch (blockIdx.z) {
        case 0:  A = Wq1; B = W_intra; ldb = 2*D; off = 0; C = g_M;  alpha = SCALE; break;
        case 1:  A = Wq1; B = W_intra; ldb = 2*D; off = D; C = g_WD; alpha = 1.f;   break;
        default: A = Wq2; B = W_inter; ldb = D;   off = 0; C = g_WQ; alpha = 1.f;   break;
    }
    __shared__ float As[GBM][GBK + 1];
    __shared__ float Bs[GBK][GBN];
    const int t = threadIdx.x;
    const int tx = t & 15, ty = t >> 4;
    const int m0 = blockIdx.y * GBM, n0 = blockIdx.x * GBN;
    float acc[4][4] = {};
    for (int k0 = 0; k0 < D; k0 += GBK) {
        for (int x = t; x < GBM*GBK; x += 256) {
            int m = x >> 4, k = x & 15;
            As[m][k] = A[(size_t)(m0 + m)*D + k0 + k];
        }
        for (int x = t; x < GBK*GBN; x += 256) {
            int k = x >> 6, n = x & 63;
            Bs[k][n] = B[(size_t)(k0 + k)*ldb + off + n0 + n];
        }
        __syncthreads();
        #pragma unroll
        for (int kk = 0; kk < GBK; kk++) {
            float a[4], w[4];
            #pragma unroll
            for (int u = 0; u < 4; u++) a[u] = As[ty*4 + u][kk];
            #pragma unroll
            for (int v = 0; v < 4; v++) w[v] = Bs[kk][tx*4 + v];
            #pragma unroll
            for (int u = 0; u < 4; u++)
                #pragma unroll
                for (int v = 0; v < 4; v++) acc[u][v] += a[u] * w[v];
        }
        __syncthreads();
    }
    #pragma unroll
    for (int u = 0; u < 4; u++)
        #pragma unroll
        for (int v = 0; v < 4; v++)
            C[(size_t)(m0 + ty*4 + u)*D + n0 + tx*4 + v] = alpha * acc[u][v];
}

// ---- batched N x D : C = alpha * (U @ W^T + bias)  (nt form) ----
__global__ void __launch_bounds__(256)
k_gemmND(const float* __restrict__ U,
         const float* __restrict__ Wk1, const float* __restrict__ bk1,
         const float* __restrict__ Wv1, const float* __restrict__ bv1) {
    const float* W; const float* bias; float* C; float alpha;
    switch (blockIdx.z) {
        case 0:  W = Wk1;  bias = bk1;  C = g_K1; alpha = 1.f;   break;
        case 1:  W = Wv1;  bias = bv1;  C = g_V1; alpha = 1.f;   break;
        case 2:  W = g_WD; bias = g_bD; C = g_D1; alpha = SCALE; break;
        default: W = g_WQ; bias = g_bQ; C = g_Q2; alpha = 1.f;   break;
    }
    __shared__ float As[GBM][GBK + 1];
    __shared__ float Ws[GBN][GBK + 1];
    const int t = threadIdx.x;
    const int tx = t & 15, ty = t >> 4;
    const int m0 = blockIdx.y * GBM, n0 = blockIdx.x * GBN;
    float acc[4][4] = {};
    for (int k0 = 0; k0 < D; k0 += GBK) {
        for (int x = t; x < GBM*GBK; x += 256) {
            int m = x >> 4, k = x & 15;
            As[m][k] = U[(size_t)(m0 + m)*D + k0 + k];
        }
        for (int x = t; x < GBN*GBK; x += 256) {
            int n = x >> 4, k = x & 15;
            Ws[n][k] = W[(size_t)(n0 + n)*D + k0 + k];
        }
        __syncthreads();
        #pragma unroll
        for (int kk = 0; kk < GBK; kk++) {
            float a[4], w[4];
            #pragma unroll
            for (int u = 0; u < 4; u++) a[u] = As[ty*4 + u][kk];
            #pragma unroll
            for (int v = 0; v < 4; v++) w[v] = Ws[tx*4 + v][kk];
            #pragma unroll
            for (int u = 0; u < 4; u++)
                #pragma unroll
                for (int v = 0; v < 4; v++) acc[u][v] += a[u] * w[v];
        }
        __syncthreads();
    }
    #pragma unroll
    for (int u = 0; u < 4; u++)
        #pragma unroll
        for (int v = 0; v < 4; v++) {
            int m = m0 + ty*4 + u, n = n0 + tx*4 + v;
            C[(size_t)m*D + n] = alpha * (acc[u][v] + bias[n]);
        }
}

// ---- generic N x D ab-form : C = alpha * A @ B  (B is D x D row-major) ----
__device__ __forceinline__ void gemm_ab_body(const float* __restrict__ A,
                                             const float* __restrict__ B,
                                             float* __restrict__ C, float alpha) {
    __shared__ float As[GBM][GBK + 1];
    __shared__ float Bs[GBK][GBN];
    const int t = threadIdx.x;
    const int tx = t & 15, ty = t >> 4;
    const int m0 = blockIdx.y * GBM, n0 = blockIdx.x * GBN;
    float acc[4][4] = {};
    for (int k0 = 0; k0 < D; k0 += GBK) {
        for (int x = t; x < GBM*GBK; x += 256) {
            int m = x >> 4, k = x & 15;
            As[m][k] = A[(size_t)(m0 + m)*D + k0 + k];
        }
        for (int x = t; x < GBK*GBN; x += 256) {
            int k = x >> 6, n = x & 63;
            Bs[k][n] = B[(size_t)(k0 + k)*D + n0 + n];
        }
        __syncthreads();
        #pragma unroll
        for (int kk = 0; kk < GBK; kk++) {
            float a[4], w[4];
            #pragma unroll
            for (int u = 0; u < 4; u++) a[u] = As[ty*4 + u][kk];
            #pragma unroll
            for (int v = 0; v < 4; v++) w[v] = Bs[kk][tx*4 + v];
            #pragma unroll
            for (int u = 0; u < 4; u++)
                #pragma unroll
                for (int v = 0; v < 4; v++) acc[u][v] += a[u] * w[v];
        }
        __syncthreads();
    }
    #pragma unroll
    for (int u = 0; u < 4; u++)
        #pragma unroll
        for (int v = 0; v < 4; v++)
            C[(size_t)(m0 + ty*4 + u)*D + n0 + tx*4 + v] = alpha * acc[u][v];
}

__global__ void __launch_bounds__(256)
k_gemmPost1(const float* __restrict__ Wk2) {
    if (blockIdx.z == 0) gemm_ab_body(g_Q2, Wk2, g_Z2, SCALE);
    else                 gemm_ab_body(g_K1, g_M, g_KM, 1.f);
}

__global__ void __launch_bounds__(256)
k_gemmPost2(const float* __restrict__ Wv2) {
    if (blockIdx.z == 0) gemm_ab_body(g_Z2, Wv2, g_ZW, 1.f);
    else                 gemm_ab_body(g_KM, Wv2, g_KMW, 1.f);
}

// ---- S1b = D1 @ K1^T  (N x N, nt form) ----
__global__ void __launch_bounds__(256)
k_gemmS1b() {
    __shared__ float As[GBM][GBK + 1];
    __shared__ float Ws[GBN][GBK + 1];
    const int t = threadIdx.x;
    const int tx = t & 15, ty = t >> 4;
    const int m0 = blockIdx.y * GBM, n0 = blockIdx.x * GBN;
    float acc[4][4] = {};
    for (int k0 = 0; k0 < D; k0 += GBK) {
        for (int x = t; x < GBM*GBK; x += 256) {
            int m = x >> 4, k = x & 15;
            As[m][k] = g_D1[(size_t)(m0 + m)*D + k0 + k];
        }
        for (int x = t; x < GBN*GBK; x += 256) {
            int n = x >> 4, k = x & 15;
            Ws[n][k] = g_K1[(size_t)(n0 + n)*D + k0 + k];
        }
        __syncthreads();
        #pragma unroll
        for (int kk = 0; kk < GBK; kk++) {
            float a[4], w[4];
            #pragma unroll
            for (int u = 0; u < 4; u++) a[u] = As[ty*4 + u][kk];
            #pragma unroll
            for (int v = 0; v < 4; v++) w[v] = Ws[tx*4 + v][kk];
            #pragma unroll
            for (int u = 0; u < 4; u++)
                #pragma unroll
                for (int v = 0; v < 4; v++) acc[u][v] += a[u] * w[v];
        }
        __syncthreads();
    }
    #pragma unroll
    for (int u = 0; u < 4; u++)
        #pragma unroll
        for (int v = 0; v < 4; v++)
            g_S1b[(size_t)(m0 + ty*4 + u)*N + n0 + tx*4 + v] = acc[u][v];
}

// ================= main recurrence: ONE grid barrier per step =================
__global__ void __launch_bounds__(NT, 1)
k_main(const float* __restrict__ U,
       const float* __restrict__ Wv2, const float* __restrict__ bv2,
       float* __restrict__ Vout) {
    extern __shared__ float sm[];
    float* sWv2  = sm + OFF_WV2;
    float* sY1   = sm + OFF_Y1;
    float* sY2   = sm + OFF_Y2;
    float* sVt   = sm + OFF_VT;
    float* sZ2   = sm + OFF_Z2;
    int*   sTmpI = (int*)(sm + OFF_TMPI);

    __shared__ float sE1[NWARP], sE2[NWARP];

    const int b = blockIdx.x, t = threadIdx.x;
    const int warp = t >> 5, lane = t & 31;
    const int gwid = b * NWARP + warp;

    // one-time: Wv2 rows + tmp[] into SMEM
    for (int x = t; x < RPB*D; x += NT)
        sWv2[x] = Wv2[(size_t)(b*RPB)*D + x];
    for (int x = t; x < N; x += NT) sTmpI[x] = g_tmp[x];
    __syncthreads();

    unsigned long long nbar = 0;

    for (int i = 0; i <= N; i++) {
        const int tmp = (i < N) ? sTmpI[i] : -1;
        const int p = i % 3, q = (i + 2) % 3, z = (i + 1) % 3;
        bool hv = false;
        const bool fresh = (i > 0) && (tmp == i - 1);

        // ---- build y1/y2 (implicit V[i-1] = y1 + Wv2*y2) ----
        if (i > 0) {
            const int tprev = sTmpI[i-1];
            hv = (tprev >= 0);
            if (hv) {
                const float s1i = 1.0f / g_sum1[q];
                const float s2i = 1.0f / g_sum2[q];
                const float ph  = g_phi[q];
                const float* vp2 = Vout + (size_t)(i-2)*D;   // i>=2 guaranteed when hv
                for (int c = t; c < D; c += NT) {
                    sY1[c] = g_vacc1[q][c] * s1i + bv2[c];
                    sY2[c] = (g_vaccV[q][c] + ph * vp2[c]) * s2i;
                }
            } else {
                const float* ur = U + (size_t)(i-1)*D;
                for (int c = t; c < D; c += NT) { sY1[c] = ur[c]; sY2[c] = 0.f; }
            }
        }
        if (tmp >= 0) {
            const float* z2r = g_Z2 + (size_t)i*D;
            for (int c = t; c < D; c += NT) sZ2[c] = z2r[c];
            if (!fresh) {
                const float* vt = Vout + (size_t)tmp*D;
                for (int c = t; c < D; c += NT) sVt[c] = vt[c];
            }
        }
        // zero slot z (block-owned columns; sums by block 0)
        if (t < RPB) {
            g_vacc1[z][b*RPB + t] = 0.f;
            g_vaccV[z][b*RPB + t] = 0.f;
        }
        if (b == 0 && t == 0) { g_sum1[z] = 0.f; g_sum2[z] = 0.f; g_phi[z] = 0.f; }
        __syncthreads();

        int n1 = 0, n2 = 0;
        if (tmp >= 0) {
            n1 = i + 1 - b*NWARP;        if (n1 < 0) n1 = 0; if (n1 > NWARP) n1 = NWARP;
            n2 = i - 1 - tmp - b*NWARP;  if (n2 < 0) n2 = 0; if (n2 > NWARP) n2 = NWARP;

            // intra score: row j = gwid (<= i)
            {
                float e1 = 0.f;
                if (gwid <= i) {
                    float a;
                    if (fresh) {
                        a = wdot(g_KM + (size_t)gwid*D, sY1, lane);
                        if (hv) a += wdot(g_KMW + (size_t)gwid*D, sY2, lane);
                    } else {
                        a = wdot(g_KM + (size_t)gwid*D, sVt, lane);
                    }
                    a = wreduce(a);
                    e1 = __expf(a + g_S1b[(size_t)i*N + gwid]);
                }
                if (lane == 0) sE1[warp] = e1;
            }
            // inter direct score: row j = tmp + gwid (<= i-2)
            {
                const int j = tmp + gwid;
                float e2 = 0.f;
                if (j <= i - 2) {
                    float a = wreduce(wdot(Vout + (size_t)j*D, sZ2, lane));
                    e2 = __expf(a);
                }
                if (lane == 0) sE2[warp] = e2;
            }
            // fresh inter row j = i-1 (deferred via phi)
            if (gwid == i - 1 - tmp) {
                float a = wdot(sZ2, sY1, lane);
                if (hv) a += wdot(g_ZW + (size_t)i*D, sY2, lane);
                a = wreduce(a);
                if (lane == 0) {
                    const float e = __expf(a);
                    atomicAdd(&g_sum2[p], e);
                    g_phi[p] = e;
                }
            }
        }
        // ---- finalize V[i-1]: block-owned rows ----
        if (i > 0 && warp < RPB) {
            const int r = b*RPB + warp;
            float a = 0.f;
            if (hv) a = wreduce(wdot(sWv2 + warp*D, sY2, lane));
            if (lane == 0) Vout[(size_t)(i-1)*D + r] = sY1[r] + a;
        }
        if (i == N) break;
        __syncthreads();

        if (tmp >= 0) {
            // block sums -> global
            if (warp == 0) {
                float v1 = (lane < NWARP) ? sE1[lane] : 0.f;
                float v2 = (lane < NWARP) ? sE2[lane] : 0.f;
                v1 = wreduce(v1); v2 = wreduce(v2);
                if (lane == 0) {
                    if (v1 != 0.f) atomicAdd(&g_sum1[p], v1);
                    if (v2 != 0.f) atomicAdd(&g_sum2[p], v2);
                }
            }
            // column accumulation: one global atomic per column per block
            for (int c = t; c < D; c += NT) {
                if (n1) {
                    float a = 0.f;
                    for (int k = 0; k < n1; k++)
                        a += sE1[k] * g_V1[(size_t)(b*NWARP + k)*D + c];
                    atomicAdd(&g_vacc1[p][c], a);
                }
                if (n2) {
                    float a = 0.f;
                    for (int k = 0; k < n2; k++)
                        a += sE2[k] * Vout[(size_t)(tmp + b*NWARP + k)*D + c];
                    atomicAdd(&g_vaccV[p][c], a);
                }
            }
        }
        grid_bar(b, nbar);
    }
}

// ---------------- launch ----------------
extern "C" void kernel_launch(void* const* d_in, const int* in_sizes, int n_in,
                              void* d_out, int out_size) {
    const float* U       = (const float*)d_in[0];
    const int*   spk     = (const int*)  d_in[1];
    const float* W_intra = (const float*)d_in[2];
    const float* b_intra = (const float*)d_in[3];
    const float* W_inter = (const float*)d_in[4];
    const float* b_inter = (const float*)d_in[5];
    const float* Wq1 = (const float*)d_in[6];  const float* bq1 = (const float*)d_in[7];
    const float* Wk1 = (const float*)d_in[8];  const float* bk1 = (const float*)d_in[9];
    const float* Wv1 = (const float*)d_in[10]; const float* bv1 = (const float*)d_in[11];
    const float* Wq2 = (const float*)d_in[12]; const float* bq2 = (const float*)d_in[13];
    const float* Wk2 = (const float*)d_in[14]; const float* bk2 = (const float*)d_in[15];
    const float* Wv2 = (const float*)d_in[16]; const float* bv2 = (const float*)d_in[17];
    float* Vout = (float*)d_out;
    (void)in_sizes; (void)n_in; (void)out_size; (void)bk2;

    cudaFuncSetAttribute(k_main, cudaFuncAttributeMaxDynamicSharedMemorySize, SMEM_BYTES);

    k_setup<<<101, NT>>>(spk, Wq1, bq1, b_intra, Wq2, bq2, b_inter);          // 1
    k_gemmDD<<<dim3(D/GBN, D/GBM, 3), 256>>>(Wq1, W_intra, Wq2, W_inter);     // 2
    k_gemmND<<<dim3(D/GBN, N/GBM, 4), 256>>>(U, Wk1, bk1, Wv1, bv1);          // 3
    k_gemmPost1<<<dim3(D/GBN, N/GBM, 2), 256>>>(Wk2);                         // 4
    k_gemmPost2<<<dim3(D/GBN, N/GBM, 2), 256>>>(Wv2);                         // 5
    k_gemmS1b<<<dim3(N/GBN, N/GBM), 256>>>();                                 // 6
    k_main<<<NB, NT, SMEM_BYTES>>>(U, Wv2, bv2, Vout);                        // 7
}

// round 7
// speedup vs baseline: 1.7196x; 1.0649x over previous
#include <cuda_runtime.h>
#include <math.h>

#define N 2048
#define D 768
#define SCALE 0.036084391824351615f  /* 1/sqrt(768) */

#define NB 128
#define NT 512
#define NWARP (NT/32)     /* 16 */
#define RPB (D / NB)      /* 6 rows per block */
#define NSL 3             /* triple-buffered accumulators */

/* k_main dynamic smem layout (float slots) */
#define OFF_WV2   0
#define OFF_Y1    (RPB*D)
#define OFF_Y2    (RPB*D + D)
#define OFF_VT    (RPB*D + 2*D)
#define OFF_Z2    (RPB*D + 3*D)
#define OFF_TMPI  (RPB*D + 4*D)
#define SMEM_FLOATS (RPB*D + 4*D + N)
#define SMEM_BYTES  (SMEM_FLOATS * 4)

// ---------------- device globals ----------------
__device__ float g_K1[N*D];
__device__ float g_V1[N*D];
__device__ float g_D1[N*D];            // scale*(U@WD^T + bD)
__device__ float g_Q2[N*D];
__device__ float g_Z2[N*D];            // scale*(Q2@Wk2)
__device__ float g_KM[N*D];            // K1 @ M
__device__ float g_ZW[N*D];            // scale*(Q2 @ W2V) == Z2 @ Wv2
__device__ float g_KMW[N*D];           // K1 @ MW == KM @ Wv2
__device__ float g_S1b[(size_t)N*N];   // D1 @ K1^T
__device__ float g_M [D*D];            // scale*(Wq1 @ W_intra[:, :D])
__device__ float g_WD[D*D];
__device__ float g_WQ[D*D];
__device__ float g_W2V[D*D];           // Wk2 @ Wv2
__device__ float g_MW[D*D];            // M @ Wv2
__device__ float g_bD[D];
__device__ float g_bQ[D];
__device__ float g_vacc1[NSL][D];
__device__ float g_vaccV[NSL][D];
__device__ float g_sum1[NSL];
__device__ float g_sum2[NSL];
__device__ float g_phi[NSL];
__device__ int   g_tmp[N];
__device__ unsigned long long g_root;

// ---------------- helpers ----------------
__device__ __forceinline__ float wreduce(float a) {
    #pragma unroll
    for (int o = 16; o; o >>= 1) a += __shfl_xor_sync(0xffffffffu, a, o);
    return a;
}

// warp dot over D=768 (192 float4 = 32 lanes x 6)
__device__ __forceinline__ float wdot(const float* __restrict__ a,
                                      const float* __restrict__ b, int lane) {
    const float4* A = (const float4*)a;
    const float4* B = (const float4*)b;
    float s = 0.f;
    #pragma unroll
    for (int u = 0; u < 6; u++) {
        float4 x = A[lane + 32*u], y = B[lane + 32*u];
        s += x.x*y.x + x.y*y.y + x.z*y.z + x.w*y.w;
    }
    return s;
}

// fence-free grid barrier: release-arrive + acquire-poll on one counter.
// No gpu-scope fence => no CCTL.IVALL => L1D stays warm across steps.
__device__ __forceinline__ void grid_bar(unsigned long long& nbar) {
    __syncthreads();
    if (threadIdx.x == 0) {
        unsigned long long one = 1ULL;
        asm volatile("red.release.gpu.add.u64 [%0], %1;"
                     :: "l"(&g_root), "l"(one) : "memory");
        const unsigned long long tgt = (nbar + 1) * (unsigned long long)NB;
        unsigned long long v;
        do {
            asm volatile("ld.acquire.gpu.u64 %0, [%1];"
                         : "=l"(v) : "l"(&g_root) : "memory");
        } while (v < tgt);
    }
    nbar++;
    __syncthreads();
}

// ================= GEMM tile bodies (parameterized by m0,n0) =================
#define GBM 64
#define GBN 64
#define GBK 16

// C[m0:,n0:] = alpha * A @ B[:, boff:boff+D]   (A is M x D row-major; B row-major ldb)
__device__ __forceinline__ void gemm_ab_body(const float* __restrict__ A,
                                             const float* __restrict__ B,
                                             int ldb, int boff,
                                             float* __restrict__ C,
                                             int m0, int n0, float alpha) {
    __shared__ float As[GBM][GBK + 1];
    __shared__ float Bs[GBK][GBN];
    const int t = threadIdx.x;
    const int tx = t & 15, ty = t >> 4;
    float acc[4][4] = {};
    for (int k0 = 0; k0 < D; k0 += GBK) {
        for (int x = t; x < GBM*GBK; x += 256) {
            int m = x >> 4, k = x & 15;
            As[m][k] = A[(size_t)(m0 + m)*D + k0 + k];
        }
        for (int x = t; x < GBK*GBN; x += 256) {
            int k = x >> 6, n = x & 63;
            Bs[k][n] = B[(size_t)(k0 + k)*ldb + boff + n0 + n];
        }
        __syncthreads();
        #pragma unroll
        for (int kk = 0; kk < GBK; kk++) {
            float a[4], w[4];
            #pragma unroll
            for (int u = 0; u < 4; u++) a[u] = As[ty*4 + u][kk];
            #pragma unroll
            for (int v = 0; v < 4; v++) w[v] = Bs[kk][tx*4 + v];
            #pragma unroll
            for (int u = 0; u < 4; u++)
                #pragma unroll
                for (int v = 0; v < 4; v++) acc[u][v] += a[u] * w[v];
        }
        __syncthreads();
    }
    #pragma unroll
    for (int u = 0; u < 4; u++)
        #pragma unroll
        for (int v = 0; v < 4; v++)
            C[(size_t)(m0 + ty*4 + u)*D + n0 + tx*4 + v] = alpha * acc[u][v];
}

// C[m0:,n0:] = alpha * (A @ W^T + bias)   (A: M x D; W: Nc x D; C ld = ldc)
__device__ __forceinline__ void gemm_nt_body(const float* __restrict__ A,
                                             const float* __restrict__ W,
                                             const float* __restrict__ bias,
                                             float* __restrict__ C, int ldc,
                                             int m0, int n0, float alpha) {
    __shared__ float As[GBM][GBK + 1];
    __shared__ float Ws[GBN][GBK + 1];
    const int t = threadIdx.x;
    const int tx = t & 15, ty = t >> 4;
    float acc[4][4] = {};
    for (int k0 = 0; k0 < D; k0 += GBK) {
        for (int x = t; x < GBM*GBK; x += 256) {
            int m = x >> 4, k = x & 15;
            As[m][k] = A[(size_t)(m0 + m)*D + k0 + k];
        }
        for (int x = t; x < GBN*GBK; x += 256) {
            int n = x >> 4, k = x & 15;
            Ws[n][k] = W[(size_t)(n0 + n)*D + k0 + k];
        }
        __syncthreads();
        #pragma unroll
        for (int kk = 0; kk < GBK; kk++) {
            float a[4], w[4];
            #pragma unroll
            for (int u = 0; u < 4; u++) a[u] = As[ty*4 + u][kk];
            #pragma unroll
            for (int v = 0; v < 4; v++) w[v] = Ws[tx*4 + v][kk];
            #pragma unroll
            for (int u = 0; u < 4; u++)
                #pragma unroll
                for (int v = 0; v < 4; v++) acc[u][v] += a[u] * w[v];
        }
        __syncthreads();
    }
    #pragma unroll
    for (int u = 0; u < 4; u++)
        #pragma unroll
        for (int v = 0; v < 4; v++) {
            int m = m0 + ty*4 + u, n = n0 + tx*4 + v;
            float bb = bias ? bias[n] : 0.f;
            C[(size_t)m*ldc + n] = alpha * (acc[u][v] + bb);
        }
}

// ================= pre1: DD GEMMs {M, WD, WQ, W2V} + setup =================
__global__ void __launch_bounds__(256)
k_pre1(const int* __restrict__ spk,
       const float* __restrict__ Wq1, const float* __restrict__ bq1,
       const float* __restrict__ b_intra,
       const float* __restrict__ Wq2, const float* __restrict__ bq2,
       const float* __restrict__ b_inter,
       const float* __restrict__ W_intra, const float* __restrict__ W_inter,
       const float* __restrict__ Wk2, const float* __restrict__ Wv2) {
    const int blk = blockIdx.x, t = threadIdx.x;
    if (blk < 576) {
        const int z = blk / 144, id = blk % 144;
        const int m0 = (id / 12) * GBM, n0 = (id % 12) * GBN;
        switch (z) {
            case 0: gemm_ab_body(Wq1, W_intra, 2*D, 0, g_M,  m0, n0, SCALE); break;
            case 1: gemm_ab_body(Wq1, W_intra, 2*D, D, g_WD, m0, n0, 1.f);   break;
            case 2: gemm_ab_body(Wq2, W_inter, D,   0, g_WQ, m0, n0, 1.f);   break;
            default: gemm_ab_body(Wk2, Wv2,    D,   0, g_W2V, m0, n0, 1.f);  break;
        }
    } else {
        const int sb = blk - 576;
        if (sb < 8) {
            // last_same back-scan
            int i = sb * 256 + t;
            int s = spk[i], r = -1;
            for (int j = i - 1; j >= 0; j--)
                if (spk[j] == s) { r = j; break; }
            g_tmp[i] = r;
        } else if (sb < 200) {
            const int rid = (sb - 8) * 8 + (t >> 5);   // 0..1535
            const int lane = t & 31;
            const int mat = rid >= D;
            const int r = mat ? rid - D : rid;
            const float* W  = mat ? Wq2 : Wq1;
            const float* bv = mat ? b_inter : b_intra;
            float a = 0.f;
            for (int k = lane; k < D; k += 32) a += W[(size_t)r*D + k] * bv[k];
            a = wreduce(a);
            if (lane == 0) {
                if (mat) g_bQ[r] = a + bq2[r];
                else     g_bD[r] = a + bq1[r];
            }
        } else {
            // state reset (graph replays!)
            if (t == 0) {
                g_root = 0ULL;
                for (int s = 0; s < NSL; s++) {
                    g_sum1[s] = 0.f; g_sum2[s] = 0.f; g_phi[s] = 0.f;
                }
            }
            for (int c = t; c < D; c += 256)
                for (int s = 0; s < NSL; s++) {
                    g_vacc1[s][c] = 0.f; g_vaccV[s][c] = 0.f;
                }
        }
    }
}

// ================= pre2: ND GEMMs {K1, V1, D1, Q2} + MW =================
__global__ void __launch_bounds__(256)
k_pre2(const float* __restrict__ U,
       const float* __restrict__ Wk1, const float* __restrict__ bk1,
       const float* __restrict__ Wv1, const float* __restrict__ bv1,
       const float* __restrict__ Wv2) {
    const int blk = blockIdx.x;
    if (blk < 1536) {
        const int z = blk / 384, id = blk % 384;
        const int m0 = (id / 12) * GBM, n0 = (id % 12) * GBN;
        switch (z) {
            case 0: gemm_nt_body(U, Wk1,  bk1,  g_K1, D, m0, n0, 1.f);   break;
            case 1: gemm_nt_body(U, Wv1,  bv1,  g_V1, D, m0, n0, 1.f);   break;
            case 2: gemm_nt_body(U, g_WD, g_bD, g_D1, D, m0, n0, SCALE); break;
            default: gemm_nt_body(U, g_WQ, g_bQ, g_Q2, D, m0, n0, 1.f);  break;
        }
    } else {
        const int id = blk - 1536;   // 0..143 : MW = M @ Wv2
        const int m0 = (id / 12) * GBM, n0 = (id % 12) * GBN;
        gemm_ab_body(g_M, Wv2, D, 0, g_MW, m0, n0, 1.f);
    }
}

// ================= pre3: post GEMMs {Z2, KM, ZW, KMW} + S1b =================
__global__ void __launch_bounds__(256)
k_pre3(const float* __restrict__ Wk2) {
    const int blk = blockIdx.x;
    if (blk < 1536) {
        const int z = blk / 384, id = blk % 384;
        const int m0 = (id / 12) * GBM, n0 = (id % 12) * GBN;
        switch (z) {
            case 0: gemm_ab_body(g_Q2, Wk2,   D, 0, g_Z2,  m0, n0, SCALE); break;
            case 1: gemm_ab_body(g_K1, g_M,   D, 0, g_KM,  m0, n0, 1.f);   break;
            case 2: gemm_ab_body(g_Q2, g_W2V, D, 0, g_ZW,  m0, n0, SCALE); break;
            default: gemm_ab_body(g_K1, g_MW, D, 0, g_KMW, m0, n0, 1.f);   break;
        }
    } else {
        const int id = blk - 1536;   // 0..1023 : S1b = D1 @ K1^T (N x N)
        const int m0 = (id / 32) * GBM, n0 = (id % 32) * GBN;
        gemm_nt_body(g_D1, g_K1, (const float*)0, g_S1b, N, m0, n0, 1.f);
    }
}

// ================= main recurrence: ONE fence-free barrier per step =================
__global__ void __launch_bounds__(NT, 1)
k_main(const float* __restrict__ U,
       const float* __restrict__ Wv2, const float* __restrict__ bv2,
       float* __restrict__ Vout) {
    extern __shared__ float sm[];
    float* sWv2  = sm + OFF_WV2;
    float* sY1   = sm + OFF_Y1;
    float* sY2   = sm + OFF_Y2;
    float* sVt   = sm + OFF_VT;
    float* sZ2   = sm + OFF_Z2;
    int*   sTmpI = (int*)(sm + OFF_TMPI);

    __shared__ float sE1[NWARP], sE2[NWARP];

    const int b = blockIdx.x, t = threadIdx.x;
    const int warp = t >> 5, lane = t & 31;
    const int gwid = b * NWARP + warp;

    // one-time: Wv2 rows + tmp[] into SMEM
    for (int x = t; x < RPB*D; x += NT)
        sWv2[x] = Wv2[(size_t)(b*RPB)*D + x];
    for (int x = t; x < N; x += NT) sTmpI[x] = g_tmp[x];
    __syncthreads();

    unsigned long long nbar = 0;

    for (int i = 0; i <= N; i++) {
        const int tmp = (i < N) ? sTmpI[i] : -1;
        const int p = i % 3, q = (i + 2) % 3, z = (i + 1) % 3;
        bool hv = false;
        const bool fresh = (i > 0) && (tmp == i - 1);

        // ---- build y1/y2 (implicit V[i-1] = y1 + Wv2*y2) ----
        // mutable cross-step state is read via __ldcg (L2) — L1 is never
        // invalidated, so read-only arrays stay L1-resident across steps.
        if (i > 0) {
            const int tprev = sTmpI[i-1];
            hv = (tprev >= 0);
            if (hv) {
                const float s1i = 1.0f / __ldcg(&g_sum1[q]);
                const float s2i = 1.0f / __ldcg(&g_sum2[q]);
                const float ph  = __ldcg(&g_phi[q]);
                const float* vp2 = Vout + (size_t)(i-2)*D;   // i>=2 when hv
                for (int c = t; c < D; c += NT) {
                    sY1[c] = __ldcg(&g_vacc1[q][c]) * s1i + bv2[c];
                    sY2[c] = (__ldcg(&g_vaccV[q][c]) + ph * vp2[c]) * s2i;
                }
            } else {
                const float* ur = U + (size_t)(i-1)*D;
                for (int c = t; c < D; c += NT) { sY1[c] = ur[c]; sY2[c] = 0.f; }
            }
        }
        if (tmp >= 0) {
            const float* z2r = g_Z2 + (size_t)i*D;
            for (int c = t; c < D; c += NT) sZ2[c] = z2r[c];
            if (!fresh) {
                const float* vt = Vout + (size_t)tmp*D;
                for (int c = t; c < D; c += NT) sVt[c] = vt[c];
            }
        }
        // zero slot z (block-owned columns; sums by block 0)
        if (t < RPB) {
            g_vacc1[z][b*RPB + t] = 0.f;
            g_vaccV[z][b*RPB + t] = 0.f;
        }
        if (b == 0 && t == 0) { g_sum1[z] = 0.f; g_sum2[z] = 0.f; g_phi[z] = 0.f; }
        __syncthreads();

        int n1 = 0, n2 = 0;
        if (tmp >= 0) {
            n1 = i + 1 - b*NWARP;        if (n1 < 0) n1 = 0; if (n1 > NWARP) n1 = NWARP;
            n2 = i - 1 - tmp - b*NWARP;  if (n2 < 0) n2 = 0; if (n2 > NWARP) n2 = NWARP;

            // intra score: row j = gwid (<= i)
            {
                float e1 = 0.f;
                if (gwid <= i) {
                    float a;
                    if (fresh) {
                        a = wdot(g_KM + (size_t)gwid*D, sY1, lane);
                        if (hv) a += wdot(g_KMW + (size_t)gwid*D, sY2, lane);
                    } else {
                        a = wdot(g_KM + (size_t)gwid*D, sVt, lane);
                    }
                    a = wreduce(a);
                    e1 = __expf(a + g_S1b[(size_t)i*N + gwid]);
                }
                if (lane == 0) sE1[warp] = e1;
            }
            // inter direct score: row j = tmp + gwid (<= i-2)
            {
                const int j = tmp + gwid;
                float e2 = 0.f;
                if (j <= i - 2) {
                    float a = wreduce(wdot(Vout + (size_t)j*D, sZ2, lane));
                    e2 = __expf(a);
                }
                if (lane == 0) sE2[warp] = e2;
            }
            // fresh inter row j = i-1 (deferred via phi)
            if (gwid == i - 1 - tmp) {
                float a = wdot(sZ2, sY1, lane);
                if (hv) a += wdot(g_ZW + (size_t)i*D, sY2, lane);
                a = wreduce(a);
                if (lane == 0) {
                    const float e = __expf(a);
                    atomicAdd(&g_sum2[p], e);
                    g_phi[p] = e;
                }
            }
        }
        // ---- finalize V[i-1]: block-owned rows ----
        if (i > 0 && warp < RPB) {
            const int r = b*RPB + warp;
            float a = 0.f;
            if (hv) a = wreduce(wdot(sWv2 + warp*D, sY2, lane));
            if (lane == 0) Vout[(size_t)(i-1)*D + r] = sY1[r] + a;
        }
        if (i == N) break;
        __syncthreads();

        if (tmp >= 0) {
            // block sums -> global
            if (warp == 0) {
                float v1 = (lane < NWARP) ? sE1[lane] : 0.f;
                float v2 = (lane < NWARP) ? sE2[lane] : 0.f;
                v1 = wreduce(v1); v2 = wreduce(v2);
                if (lane == 0) {
                    if (v1 != 0.f) atomicAdd(&g_sum1[p], v1);
                    if (v2 != 0.f) atomicAdd(&g_sum2[p], v2);
                }
            }
            // column accumulation: one global atomic per column per block
            for (int c = t; c < D; c += NT) {
                if (n1) {
                    float a = 0.f;
                    for (int k = 0; k < n1; k++)
                        a += sE1[k] * g_V1[(size_t)(b*NWARP + k)*D + c];
                    atomicAdd(&g_vacc1[p][c], a);
                }
                if (n2) {
                    float a = 0.f;
                    for (int k = 0; k < n2; k++)
                        a += sE2[k] * Vout[(size_t)(tmp + b*NWARP + k)*D + c];
                    atomicAdd(&g_vaccV[p][c], a);
                }
            }
        }
        grid_bar(nbar);
    }
}

// ---------------- launch : k_main is launch #4 ----------------
extern "C" void kernel_launch(void* const* d_in, const int* in_sizes, int n_in,
                              void* d_out, int out_size) {
    const float* U       = (const float*)d_in[0];
    const int*   spk     = (const int*)  d_in[1];
    const float* W_intra = (const float*)d_in[2];
    const float* b_intra = (const float*)d_in[3];
    const float* W_inter = (const float*)d_in[4];
    const float* b_inter = (const float*)d_in[5];
    const float* Wq1 = (const float*)d_in[6];  const float* bq1 = (const float*)d_in[7];
    const float* Wk1 = (const float*)d_in[8];  const float* bk1 = (const float*)d_in[9];
    const float* Wv1 = (const float*)d_in[10]; const float* bv1 = (const float*)d_in[11];
    const float* Wq2 = (const float*)d_in[12]; const float* bq2 = (const float*)d_in[13];
    const float* Wk2 = (const float*)d_in[14]; const float* bk2 = (const float*)d_in[15];
    const float* Wv2 = (const float*)d_in[16]; const float* bv2 = (const float*)d_in[17];
    float* Vout = (float*)d_out;
    (void)in_sizes; (void)n_in; (void)out_size; (void)bk2;

    cudaFuncSetAttribute(k_main, cudaFuncAttributeMaxDynamicSharedMemorySize, SMEM_BYTES);

    k_pre1<<<777, 256>>>(spk, Wq1, bq1, b_intra, Wq2, bq2, b_inter,
                         W_intra, W_inter, Wk2, Wv2);                 // 1
    k_pre2<<<1680, 256>>>(U, Wk1, bk1, Wv1, bv1, Wv2);                // 2
    k_pre3<<<2560, 256>>>(Wk2);                                       // 3
    k_main<<<NB, NT, SMEM_BYTES>>>(U, Wv2, bv2, Vout);                // 4
}